// round 15
// baseline (speedup 1.0000x reference)
#include <cuda_runtime.h>
#include <cuda_bf16.h>

// T=4096, B=512, n=32, deg=3. Sequential nonlinear RNN over T.
//
// R15 = R10 (champion, 552us, rel_err 1.6369585e-4) with the df-tanh spine
// compressed (the only compressible chain segment; model: 258 cyc/step =
// 132 update+pinned-sum + 20 z/poly + ~105 tanh + selects):
//   1. Cody-Waite reduction (12-bit C1 => kf*C1 exact, d exact) — removes
//      the two_sum reduction block
//   2. EARLY MUFU reciprocal: rcp(ex2.approx(2*poly*log2e)+1) computed right
//      after poly, parallel to the df assembly (correction absorbs delta^2)
//   3. no (mh,ml) renorm (downstream two_sums absorb <=2ulp ml)
//   4. ballot removed (it almost never skipped; pure chain overhead)
//   5. fmax removed (tanh>0 for poly>0; relu handled by the poly<=0 select)
// Update / sum / poly / clip-select source text VERBATIM from R10.
// Checksum: rel_err should be exactly 0.0001636959 (<=3e-4 acceptable).

static constexpr int BATCH  = 512;
static constexpr int NSTATE = 32;
static constexpr int PF     = 8;   // ring depth == unroll factor

// Compressed double-float tanh for x in (0, 9.2] (garbage-safe outside:
// result discarded by selects). abs err ~1e-9 (same class as R10's df).
__device__ __forceinline__ float tanh_df_fast(float x) {
    // ---- early reciprocal seed (MUFU chain hidden under df assembly) ----
    float E0, rcp;
    const float wh = __fmul_rn(x, 2.8853900817779268f);     // 2*log2(e)*x
    asm("ex2.approx.f32 %0, %1;" : "=f"(E0) : "f"(wh));     // ~e^{2x} (2^-22)
    const float Dap = E0 + 1.0f;
    asm("rcp.approx.f32 %0, %1;" : "=f"(rcp) : "f"(Dap));   // ~1/D

    // ---- Cody-Waite range reduction: r = 2x - k*ln2, |r| <= 0.3466 ----
    const float t  = 2.0f * x;                               // exact
    const float kf = rintf(t * 1.4426950408889634f);         // k in [0,27]
    const int   ki = (int)kf;
    const float C1 = 0.693359375f;                           // 12-bit: kf*C1 exact
    const float C2 = -2.12194440054690583e-4f;               // ln2 - C1
    const float ph = kf * C1;                                // EXACT
    const float d  = t - ph;                                 // EXACT (representable)
    const float m2 = kf * C2;
    const float rh = d - m2;
    const float rl = (d - rh) - m2;                          // residual (cancellation)

    // ---- expm1(r) as df: M = rh + r^2/2 + r^3*C(r) ----
    const float r2h = rh * rh;
    float r2l = fmaf(rh, rh, -r2h);
    r2l = fmaf(2.0f * rh, rl, r2l);

    float C = fmaf(rh, 2.4801587302e-5f, 1.9841269841e-4f);  // >= cubic tail
    C = fmaf(rh, C, 1.3888888889e-3f);
    C = fmaf(rh, C, 8.3333333333e-3f);
    C = fmaf(rh, C, 4.1666666667e-2f);
    C = fmaf(rh, C, 1.6666666667e-1f);
    const float cub = (r2h * rh) * C;

    const float q  = 0.5f * r2h;
    const float mh = rh + q;
    float ml = (rh - mh) + q;                                // quick_two_sum err
    ml = ml + (cub + (rl + 0.5f * r2l));                     // no renorm

    // ---- A = 2^k * M (df) ----
    const float pk = __int_as_float((ki + 127) << 23);
    const float ah = pk * mh;
    const float al = fmaf(pk, ml, fmaf(pk, mh, -ah));

    // ---- N = (pk - 1) + A ; D = (pk + 1) + A (full two_sums, k<=27) ----
    const float n1 = pk - 1.0f;
    const float nd = n1 - pk;
    const float ne = (pk - (n1 - nd)) + (-1.0f - nd);
    const float nh = n1 + ah;
    const float tb1 = nh - n1;
    const float nl = ((n1 - (nh - tb1)) + (ah - tb1)) + ne + al;

    const float d1 = pk + 1.0f;
    const float dd = d1 - pk;
    const float de = (pk - (d1 - dd)) + (1.0f - dd);
    const float dh = d1 + ah;
    const float tb2 = dh - d1;
    const float dl = ((d1 - (dh - tb2)) + (ah - tb2)) + de + al;

    // ---- q = N/D with one df correction (rcp already in flight) ----
    const float q0 = nh * rcp;
    const float e1 = fmaf(-q0, dh, nh);
    const float resid = e1 + fmaf(-q0, dl, nl);
    return fmaf(resid, rcp, q0);
}

__global__ void __launch_bounds__(32, 1)
rnn_firing_rate_r15(const float* __restrict__ currents,   // [T, B]
                    const float* __restrict__ a_vec,      // [n]
                    const float* __restrict__ b_vec,      // [n]
                    const float* __restrict__ ds,         // [n]
                    const float* __restrict__ poly_coeff, // [4]
                    const float* __restrict__ g_b,        // [1]
                    float* __restrict__ out,              // [T, B]
                    int T)
{
    const int batch = blockIdx.x * 32 + threadIdx.x;

    float av[NSTATE], bv[NSTATE], dec[NSTATE], v[NSTATE];
    #pragma unroll
    for (int k = 0; k < NSTATE; ++k) {
        av[k]  = a_vec[k];
        bv[k]  = b_vec[k];
        dec[k] = 1.0f - ds[k];
        v[k]   = 0.0f;
    }
    const float c0 = poly_coeff[0] * poly_coeff[0];
    const float c1 = poly_coeff[1] * poly_coeff[1];
    const float c2 = poly_coeff[2] * poly_coeff[2];
    const float c3 = poly_coeff[3] * poly_coeff[3];
    const float gbv = g_b[0];

    // current prefetch ring — static indices via unroll => registers
    float cbuf[PF];
    #pragma unroll
    for (int i = 0; i < PF; ++i)
        cbuf[i] = (i < T) ? currents[i * BATCH + batch] : 0.0f;

    const float* cptr = currents + (size_t)PF * BATCH + batch;
    float*       optr = out + batch;

    float fs = 0.0f;

    for (int tblk = 0; tblk < T; tblk += PF) {
        #pragma unroll
        for (int u = 0; u < PF; ++u) {
            const int t = tblk + u;
            const float cur = cbuf[u];
            if (t + PF < T) cbuf[u] = cptr[u * BATCH];

            const float h = 1000.0f * fs;   // feedback from PREVIOUS step

            // v[k] = decay[k]*v[k] + cur*a[k] + h*b[k]; natural-order sum.
            // VERBATIM R10 source: nvcc contraction matches the reference.
            float s = 0.0f;
            #pragma unroll
            for (int k = 0; k < NSTATE; ++k) {
                v[k] = dec[k] * v[k] + cur * av[k] + h * bv[k];
                s += v[k];
            }

            // z = mean(v) - g_b ; poly = c0 + c1 z + c2 z^2 + c3 z^3 (verbatim)
            const float z  = s * (1.0f / 32.0f) - gbv;
            const float z2 = z * z;
            const float z3 = z2 * z;
            const float poly = c0 + c1 * z + c2 * z2 + c3 * z3;

            // fs = relu(100 * tanh(poly)), branch-free:
            //   poly <= 0   -> 0      (relu)
            //   poly >  9.2 -> 100    (tanh rounds to 1.0f)
            //   else        -> compressed df tanh (always computed; selects
            //                  discard garbage outside the mid zone)
            const float th  = tanh_df_fast(poly);
            const float fsv = 100.0f * th;          // >0 in mid zone; no fmax
            fs = (poly <= 0.0f) ? 0.0f : ((poly > 9.2f) ? 100.0f : fsv);

            *optr = fs;
            optr += BATCH;
        }
        cptr += PF * BATCH;
    }
}

extern "C" void kernel_launch(void* const* d_in, const int* in_sizes, int n_in,
                              void* d_out, int out_size)
{
    const float* currents   = (const float*)d_in[0];  // [T*B]
    const float* a_vec      = (const float*)d_in[1];  // [32]
    const float* b_vec      = (const float*)d_in[2];  // [32]
    const float* ds         = (const float*)d_in[3];  // [32]
    const float* poly_coeff = (const float*)d_in[4];  // [4]
    const float* g_b        = (const float*)d_in[5];  // [1]
    float* out = (float*)d_out;

    const int T = in_sizes[0] / BATCH;                // 4096

    rnn_firing_rate_r15<<<BATCH / 32, 32>>>(currents, a_vec, b_vec, ds,
                                            poly_coeff, g_b, out, T);
}

// round 16
// speedup vs baseline: 1.0306x; 1.0306x over previous
#include <cuda_runtime.h>
#include <cuda_bf16.h>

// T=4096, B=512, n=32, deg=3. Sequential nonlinear RNN over T.
//
// R16 = R10 (champion 552us, rel_err 1.6369585e-4) byte-identical EXCEPT the
// activation block becomes two-tier:
//   outer ballot (0, 9.2]      : unchanged (R10's ~30% full-skip preserved)
//   fast MUFU tanh             : th = 1 - 2*rcp(ex2(2x*log2e)+1) w/ low-word
//                                correction; abs err ~5e-11 — 100x below the
//                                fs flip threshold in the saturated band,
//                                where 1-ulp flips are self-healing anyway
//                                (R15 evidence). Chain ~40 cyc vs df's ~115.
//   nested ballot (0, 4.75]    : verbatim df tanh only when some lane is in
//                                the transition band (where bit-exactness
//                                genuinely matters).
// Model (fits R9-R15): avg = p*skip(175) + taken; cutting taken 290->~205
// on saturated-only steps.

static constexpr int BATCH  = 512;
static constexpr int NSTATE = 32;
static constexpr int PF     = 8;   // ring depth == unroll factor

// Double-float tanh for x in (0, 4.75+] (transition zone; verbatim from R10).
__device__ __forceinline__ float tanh_df_lean(float x) {
    const float t  = 2.0f * x;
    const float kf = rintf(t * 1.4426950408889634f);
    const int   ki = (int)kf;

    const float L_h = 0.693147182464599609375f;
    const float L_l = -1.9046542996577634e-9f;
    const float ph = kf * L_h;
    const float pe = fmaf(kf, L_h, -ph);
    const float d  = t - ph;
    const float rh = d - pe;
    const float bb = rh - d;
    const float er = (d - (rh - bb)) + (-pe - bb);
    const float rl = er - kf * L_l;

    const float r2h = rh * rh;
    float r2l = fmaf(rh, rh, -r2h);
    r2l = fmaf(2.0f * rh, rl, r2l);

    float C = fmaf(rh, 2.4801587302e-5f, 1.9841269841e-4f);
    C = fmaf(rh, C, 1.3888888889e-3f);
    C = fmaf(rh, C, 8.3333333333e-3f);
    C = fmaf(rh, C, 4.1666666667e-2f);
    C = fmaf(rh, C, 1.6666666667e-1f);
    const float cub = (r2h * rh) * C;

    const float q  = 0.5f * r2h;
    float mh = rh + q;
    float ml = (rh - mh) + q;
    ml = ml + (cub + (rl + 0.5f * r2l));
    { const float s = mh + ml; ml = ml - (s - mh); mh = s; }

    const float pk = __int_as_float((ki + 127) << 23);
    const float ah = pk * mh;
    const float al = fmaf(pk, ml, fmaf(pk, mh, -ah));

    const float n1 = pk - 1.0f;
    const float nd = n1 - pk;
    const float ne = (pk - (n1 - nd)) + (-1.0f - nd);
    const float nh = n1 + ah;
    const float tb1 = nh - n1;
    const float nl = ((n1 - (nh - tb1)) + (ah - tb1)) + ne + al;

    const float d1 = pk + 1.0f;
    const float dd = d1 - pk;
    const float de = (pk - (d1 - dd)) + (1.0f - dd);
    const float dh = d1 + ah;
    const float tb2 = dh - d1;
    const float dl = ((d1 - (dh - tb2)) + (ah - tb2)) + de + al;

    float rcp;
    asm("rcp.approx.f32 %0, %1;" : "=f"(rcp) : "f"(dh));
    const float q0 = nh * rcp;
    const float e1 = fmaf(-q0, dh, nh);
    const float resid = e1 + fmaf(-q0, dl, nl);
    return fmaf(resid, rcp, q0);
}

__global__ void __launch_bounds__(32, 1)
rnn_firing_rate_r16(const float* __restrict__ currents,   // [T, B]
                    const float* __restrict__ a_vec,      // [n]
                    const float* __restrict__ b_vec,      // [n]
                    const float* __restrict__ ds,         // [n]
                    const float* __restrict__ poly_coeff, // [4]
                    const float* __restrict__ g_b,        // [1]
                    float* __restrict__ out,              // [T, B]
                    int T)
{
    const int batch = blockIdx.x * 32 + threadIdx.x;

    float av[NSTATE], bv[NSTATE], dec[NSTATE], v[NSTATE];
    #pragma unroll
    for (int k = 0; k < NSTATE; ++k) {
        av[k]  = a_vec[k];
        bv[k]  = b_vec[k];
        dec[k] = 1.0f - ds[k];
        v[k]   = 0.0f;
    }
    const float c0 = poly_coeff[0] * poly_coeff[0];
    const float c1 = poly_coeff[1] * poly_coeff[1];
    const float c2 = poly_coeff[2] * poly_coeff[2];
    const float c3 = poly_coeff[3] * poly_coeff[3];
    const float gbv = g_b[0];

    // current prefetch ring — static indices via unroll => registers
    float cbuf[PF];
    #pragma unroll
    for (int i = 0; i < PF; ++i)
        cbuf[i] = (i < T) ? currents[i * BATCH + batch] : 0.0f;

    const float* cptr = currents + (size_t)PF * BATCH + batch;
    float*       optr = out + batch;

    float fs = 0.0f;

    for (int tblk = 0; tblk < T; tblk += PF) {
        #pragma unroll
        for (int u = 0; u < PF; ++u) {
            const int t = tblk + u;
            const float cur = cbuf[u];
            if (t + PF < T) cbuf[u] = cptr[u * BATCH];

            const float h = 1000.0f * fs;   // feedback from PREVIOUS step

            // v[k] = decay[k]*v[k] + cur*a[k] + h*b[k]; natural-order sum.
            // VERBATIM R10 source: nvcc contraction matches the reference.
            float s = 0.0f;
            #pragma unroll
            for (int k = 0; k < NSTATE; ++k) {
                v[k] = dec[k] * v[k] + cur * av[k] + h * bv[k];
                s += v[k];
            }

            // z = mean(v) - g_b ; poly = c0 + c1 z + c2 z^2 + c3 z^3 (verbatim)
            const float z  = s * (1.0f / 32.0f) - gbv;
            const float z2 = z * z;
            const float z3 = z2 * z;
            const float poly = c0 + c1 * z + c2 * z2 + c3 * z3;

            // fs = relu(100 * tanh(poly)) — two-tier:
            //   poly <= 0    -> 0    ; poly > 9.2 -> 100 (exact clip zones)
            //   (4.75, 9.2]  -> fast MUFU tanh (abs err ~5e-11; self-healing
            //                   band)
            //   (0,    4.75] -> verbatim df tanh under nested ballot
            const bool mid = (poly > 0.0f) && (poly <= 9.2f);
            float fs_mid = 0.0f;
            if (__ballot_sync(0xFFFFFFFFu, mid)) {
                // fast path: th = 1 - 2/(E+1), E = e^{2*poly} via ex2 with
                // low-word argument correction (cHi+cLo = 2*log2(e)).
                const float wh = __fmul_rn(poly, 2.8853900432586670f);
                float wl = fmaf(poly, 2.8853900432586670f, -wh);
                wl = fmaf(poly, 3.8519259985e-8f, wl);
                float E0;
                asm("ex2.approx.f32 %0, %1;" : "=f"(E0) : "f"(wh));
                const float E = fmaf(E0, __fmul_rn(wl, 0.6931471805599453f), E0);
                const float D = E + 1.0f;
                float rd;
                asm("rcp.approx.f32 %0, %1;" : "=f"(rd) : "f"(D));
                float th = fmaf(-2.0f, rd, 1.0f);

                // transition band: exact df under nested ballot
                const bool lo = mid && (poly <= 4.75f);
                if (__ballot_sync(0xFFFFFFFFu, lo)) {
                    const float th_lo = tanh_df_lean(poly);
                    th = lo ? th_lo : th;
                }
                fs_mid = fmaxf(100.0f * th, 0.0f);
            }
            fs = (poly <= 0.0f) ? 0.0f : ((poly > 9.2f) ? 100.0f : fs_mid);

            *optr = fs;
            optr += BATCH;
        }
        cptr += PF * BATCH;
    }
}

extern "C" void kernel_launch(void* const* d_in, const int* in_sizes, int n_in,
                              void* d_out, int out_size)
{
    const float* currents   = (const float*)d_in[0];  // [T*B]
    const float* a_vec      = (const float*)d_in[1];  // [32]
    const float* b_vec      = (const float*)d_in[2];  // [32]
    const float* ds         = (const float*)d_in[3];  // [32]
    const float* poly_coeff = (const float*)d_in[4];  // [4]
    const float* g_b        = (const float*)d_in[5];  // [1]
    float* out = (float*)d_out;

    const int T = in_sizes[0] / BATCH;                // 4096

    rnn_firing_rate_r16<<<BATCH / 32, 32>>>(currents, a_vec, b_vec, ds,
                                            poly_coeff, g_b, out, T);
}

// round 17
// speedup vs baseline: 1.0685x; 1.0368x over previous
#include <cuda_runtime.h>
#include <cuda_bf16.h>

// T=4096, B=512, n=32, deg=3. Sequential nonlinear RNN over T.
//
// R17 = R10 (champion 552us) with ONE change to the activation:
//   - branch-free MUFU tanh for poly in (2.9, 9.2]:
//       th = 1 - 2*rcp(E+1), E = ex2(2x*log2e) with low-word argument
//       correction. abs err ~1e-9 for x>2.9 — the accuracy class R15
//       empirically proved safe (passed, benign rel_err shift).
//   - the df tanh ballot band narrows (0,9.2] -> (0,2.9], cutting its
//     taken-probability (the dominant reducible op term p*55).
// Still exactly ONE conditional block per step (branch overhead unchanged).
// Update / sum / poly / clip-select text VERBATIM from R10.

static constexpr int BATCH  = 512;
static constexpr int NSTATE = 32;
static constexpr int PF     = 8;   // ring depth == unroll factor

// Double-float tanh for x in (0, 2.9] (transition zone; verbatim from R10).
__device__ __forceinline__ float tanh_df_lean(float x) {
    const float t  = 2.0f * x;
    const float kf = rintf(t * 1.4426950408889634f);
    const int   ki = (int)kf;

    const float L_h = 0.693147182464599609375f;
    const float L_l = -1.9046542996577634e-9f;
    const float ph = kf * L_h;
    const float pe = fmaf(kf, L_h, -ph);
    const float d  = t - ph;
    const float rh = d - pe;
    const float bb = rh - d;
    const float er = (d - (rh - bb)) + (-pe - bb);
    const float rl = er - kf * L_l;

    const float r2h = rh * rh;
    float r2l = fmaf(rh, rh, -r2h);
    r2l = fmaf(2.0f * rh, rl, r2l);

    float C = fmaf(rh, 2.4801587302e-5f, 1.9841269841e-4f);
    C = fmaf(rh, C, 1.3888888889e-3f);
    C = fmaf(rh, C, 8.3333333333e-3f);
    C = fmaf(rh, C, 4.1666666667e-2f);
    C = fmaf(rh, C, 1.6666666667e-1f);
    const float cub = (r2h * rh) * C;

    const float q  = 0.5f * r2h;
    float mh = rh + q;
    float ml = (rh - mh) + q;
    ml = ml + (cub + (rl + 0.5f * r2l));
    { const float s = mh + ml; ml = ml - (s - mh); mh = s; }

    const float pk = __int_as_float((ki + 127) << 23);
    const float ah = pk * mh;
    const float al = fmaf(pk, ml, fmaf(pk, mh, -ah));

    const float n1 = pk - 1.0f;
    const float nd = n1 - pk;
    const float ne = (pk - (n1 - nd)) + (-1.0f - nd);
    const float nh = n1 + ah;
    const float tb1 = nh - n1;
    const float nl = ((n1 - (nh - tb1)) + (ah - tb1)) + ne + al;

    const float d1 = pk + 1.0f;
    const float dd = d1 - pk;
    const float de = (pk - (d1 - dd)) + (1.0f - dd);
    const float dh = d1 + ah;
    const float tb2 = dh - d1;
    const float dl = ((d1 - (dh - tb2)) + (ah - tb2)) + de + al;

    float rcp;
    asm("rcp.approx.f32 %0, %1;" : "=f"(rcp) : "f"(dh));
    const float q0 = nh * rcp;
    const float e1 = fmaf(-q0, dh, nh);
    const float resid = e1 + fmaf(-q0, dl, nl);
    return fmaf(resid, rcp, q0);
}

__global__ void __launch_bounds__(32, 1)
rnn_firing_rate_r17(const float* __restrict__ currents,   // [T, B]
                    const float* __restrict__ a_vec,      // [n]
                    const float* __restrict__ b_vec,      // [n]
                    const float* __restrict__ ds,         // [n]
                    const float* __restrict__ poly_coeff, // [4]
                    const float* __restrict__ g_b,        // [1]
                    float* __restrict__ out,              // [T, B]
                    int T)
{
    const int batch = blockIdx.x * 32 + threadIdx.x;

    float av[NSTATE], bv[NSTATE], dec[NSTATE], v[NSTATE];
    #pragma unroll
    for (int k = 0; k < NSTATE; ++k) {
        av[k]  = a_vec[k];
        bv[k]  = b_vec[k];
        dec[k] = 1.0f - ds[k];
        v[k]   = 0.0f;
    }
    const float c0 = poly_coeff[0] * poly_coeff[0];
    const float c1 = poly_coeff[1] * poly_coeff[1];
    const float c2 = poly_coeff[2] * poly_coeff[2];
    const float c3 = poly_coeff[3] * poly_coeff[3];
    const float gbv = g_b[0];

    // current prefetch ring — static indices via unroll => registers
    float cbuf[PF];
    #pragma unroll
    for (int i = 0; i < PF; ++i)
        cbuf[i] = (i < T) ? currents[i * BATCH + batch] : 0.0f;

    const float* cptr = currents + (size_t)PF * BATCH + batch;
    float*       optr = out + batch;

    float fs = 0.0f;

    for (int tblk = 0; tblk < T; tblk += PF) {
        #pragma unroll
        for (int u = 0; u < PF; ++u) {
            const int t = tblk + u;
            const float cur = cbuf[u];
            if (t + PF < T) cbuf[u] = cptr[u * BATCH];

            const float h = 1000.0f * fs;   // feedback from PREVIOUS step

            // v[k] = decay[k]*v[k] + cur*a[k] + h*b[k]; natural-order sum.
            // VERBATIM R10 source: nvcc contraction matches the reference.
            float s = 0.0f;
            #pragma unroll
            for (int k = 0; k < NSTATE; ++k) {
                v[k] = dec[k] * v[k] + cur * av[k] + h * bv[k];
                s += v[k];
            }

            // z = mean(v) - g_b ; poly = c0 + c1 z + c2 z^2 + c3 z^3 (verbatim)
            const float z  = s * (1.0f / 32.0f) - gbv;
            const float z2 = z * z;
            const float z3 = z2 * z;
            const float poly = c0 + c1 * z + c2 * z2 + c3 * z3;

            // Branch-free MUFU tanh, accurate to ~1e-9 abs for poly > 2.9:
            // th = 1 - 2/(E+1), E = e^{2*poly} via ex2 with low-word argument
            // correction (cHi + cLo = 2*log2(e)).
            const float wh = __fmul_rn(poly, 2.8853900432586670f);
            float wl = fmaf(poly, 2.8853900432586670f, -wh);
            wl = fmaf(poly, 3.8519259985e-8f, wl);
            float E0;
            asm("ex2.approx.f32 %0, %1;" : "=f"(E0) : "f"(wh));
            const float E = fmaf(E0, __fmul_rn(wl, 0.6931471805599453f), E0);
            const float D = E + 1.0f;
            float rd;
            asm("rcp.approx.f32 %0, %1;" : "=f"(rd) : "f"(D));
            float th = fmaf(-2.0f, rd, 1.0f);

            // Single ballot (same branch count as R10), band narrowed to the
            // true transition zone (0, 2.9] where df accuracy is required.
            const bool lo = (poly > 0.0f) && (poly <= 2.9f);
            if (__ballot_sync(0xFFFFFFFFu, lo)) {
                const float th_lo = tanh_df_lean(poly);
                th = lo ? th_lo : th;
            }

            // fs = relu(100 * tanh(poly)) with exact clip zones (verbatim):
            //   poly <= 0 -> 0 ; poly > 9.2 -> 100 (tanh rounds to 1.0f)
            const float fsv = fmaxf(100.0f * th, 0.0f);
            fs = (poly <= 0.0f) ? 0.0f : ((poly > 9.2f) ? 100.0f : fsv);

            *optr = fs;
            optr += BATCH;
        }
        cptr += PF * BATCH;
    }
}

extern "C" void kernel_launch(void* const* d_in, const int* in_sizes, int n_in,
                              void* d_out, int out_size)
{
    const float* currents   = (const float*)d_in[0];  // [T*B]
    const float* a_vec      = (const float*)d_in[1];  // [32]
    const float* b_vec      = (const float*)d_in[2];  // [32]
    const float* ds         = (const float*)d_in[3];  // [32]
    const float* poly_coeff = (const float*)d_in[4];  // [4]
    const float* g_b        = (const float*)d_in[5];  // [1]
    float* out = (float*)d_out;

    const int T = in_sizes[0] / BATCH;                // 4096

    rnn_firing_rate_r17<<<BATCH / 32, 32>>>(currents, a_vec, b_vec, ds,
                                            poly_coeff, g_b, out, T);
}